// round 5
// baseline (speedup 1.0000x reference)
#include <cuda_runtime.h>
#include <cstdint>
#include <cstdio>

// ---------------- problem-fixed constants ----------------
#define DD 128
#define MAXN 32000
#define MAXE 290000

// ---------------- scratch (static device globals; no allocs allowed) ----------------
__device__ __align__(16) float g_y   [MAXN * DD];
__device__ __align__(16) float g_ai  [MAXN * DD];
__device__ __align__(16) float g_aj  [MAXN * DD];
__device__ __align__(16) float g_feat[MAXN * DD];
__device__ __align__(16) float g_h   [64 * DD];
__device__ __align__(16) float g_praw[MAXN];
__device__ int g_cnt   [MAXN];
__device__ int g_rowptr[MAXN + 1];
__device__ int g_cursor[MAXN];
__device__ int g_srcs  [MAXE];
__device__ int g_aux   [256];

// ---------------- f32x2 helpers ----------------
__device__ __forceinline__ unsigned long long packdup(float v) {
    unsigned long long r;
    asm("mov.b64 %0, {%1, %1};" : "=l"(r) : "f"(v));
    return r;
}
__device__ __forceinline__ void fma2(unsigned long long& c, unsigned long long a, unsigned long long b) {
    asm("fma.rn.f32x2 %0, %1, %2, %0;" : "+l"(c) : "l"(a), "l"(b));
}
__device__ __forceinline__ void unpack2(unsigned long long v, float& lo, float& hi) {
    asm("mov.b64 {%0, %1}, %2;" : "=f"(lo), "=f"(hi) : "l"(v));
}

// ---------------- GEMM: C[M x 128] = A[M x 128] @ W[128 x 128]^T (+bias) ----------------
// 256 threads, M tile = 64. Smem k-major, NO padding:
//   Ws[k][n] stride 128 (main-loop LDS.128 over contiguous n -> conflict-free)
//   Xs[k][m] stride 64  (main-loop loads are warp-uniform broadcast)
// Staging maps lane->n (or lane->m) so STS.32 hits contiguous banks (conflict-free).
#define GEMM_SMEM_BYTES ((128 * 128 + 128 * 64) * 4)

__global__ __launch_bounds__(256, 2) void gemm128_kernel(
    const float* __restrict__ A, const float* __restrict__ W, int wstride,
    const float* __restrict__ bias, float* __restrict__ C, int M)
{
    extern __shared__ float sm[];
    float* Ws = sm;               // [128][128] k-major
    float* Xs = sm + 128 * 128;   // [128][64]  k-major
    const int tid = threadIdx.x;
    const int m0 = blockIdx.x * 64;

    // stage W: idx -> (n = idx%128 contiguous per warp, kq = idx/128 uniform per warp)
    for (int idx = tid; idx < 128 * 32; idx += 256) {
        int n = idx & 127, kq = idx >> 7, k = kq << 2;
        float4 w = *reinterpret_cast<const float4*>(W + (size_t)n * wstride + k);
        Ws[(k + 0) * 128 + n] = w.x;
        Ws[(k + 1) * 128 + n] = w.y;
        Ws[(k + 2) * 128 + n] = w.z;
        Ws[(k + 3) * 128 + n] = w.w;
    }
    // stage X: idx -> (m = idx%64 contiguous per warp, kq uniform per warp)
    for (int idx = tid; idx < 64 * 32; idx += 256) {
        int m = idx & 63, kq = idx >> 6, k = kq << 2;
        float4 v = make_float4(0.f, 0.f, 0.f, 0.f);
        if (m0 + m < M) v = *reinterpret_cast<const float4*>(A + (size_t)(m0 + m) * 128 + k);
        Xs[(k + 0) * 64 + m] = v.x;
        Xs[(k + 1) * 64 + m] = v.y;
        Xs[(k + 2) * 64 + m] = v.z;
        Xs[(k + 3) * 64 + m] = v.w;
    }
    __syncthreads();

    const int mt = tid >> 5;     // warp -> rows mt*8..mt*8+7 (4 pairs)
    const int nt = tid & 31;     // lane -> cols nt*4..nt*4+3
    const float* wp = Ws + nt * 4;
    const float* xp = Xs + mt * 8;

    unsigned long long acc[4][4];
#pragma unroll
    for (int i = 0; i < 4; i++)
#pragma unroll
        for (int j = 0; j < 4; j++) acc[i][j] = 0ull;

#pragma unroll 4
    for (int k = 0; k < 128; k++) {
        float4 w = *reinterpret_cast<const float4*>(wp + k * 128);
        unsigned long long b0 = packdup(w.x), b1 = packdup(w.y), b2 = packdup(w.z), b3 = packdup(w.w);
        const unsigned long long* ap = reinterpret_cast<const unsigned long long*>(xp + k * 64);
        unsigned long long a0 = ap[0], a1 = ap[1], a2 = ap[2], a3 = ap[3];
        fma2(acc[0][0], a0, b0); fma2(acc[0][1], a0, b1); fma2(acc[0][2], a0, b2); fma2(acc[0][3], a0, b3);
        fma2(acc[1][0], a1, b0); fma2(acc[1][1], a1, b1); fma2(acc[1][2], a1, b2); fma2(acc[1][3], a1, b3);
        fma2(acc[2][0], a2, b0); fma2(acc[2][1], a2, b1); fma2(acc[2][2], a2, b2); fma2(acc[2][3], a2, b3);
        fma2(acc[3][0], a3, b0); fma2(acc[3][1], a3, b1); fma2(acc[3][2], a3, b2); fma2(acc[3][3], a3, b3);
    }

    float bn0 = 0.f, bn1 = 0.f, bn2 = 0.f, bn3 = 0.f;
    if (bias) { bn0 = bias[nt * 4]; bn1 = bias[nt * 4 + 1]; bn2 = bias[nt * 4 + 2]; bn3 = bias[nt * 4 + 3]; }

#pragma unroll
    for (int i = 0; i < 4; i++) {
        int m = m0 + mt * 8 + 2 * i;
        float l0, h0, l1, h1, l2, h2, l3, h3;
        unpack2(acc[i][0], l0, h0); unpack2(acc[i][1], l1, h1);
        unpack2(acc[i][2], l2, h2); unpack2(acc[i][3], l3, h3);
        if (m < M) {
            float4 o; o.x = l0 + bn0; o.y = l1 + bn1; o.z = l2 + bn2; o.w = l3 + bn3;
            *reinterpret_cast<float4*>(C + (size_t)m * 128 + nt * 4) = o;
        }
        if (m + 1 < M) {
            float4 o; o.x = h0 + bn0; o.y = h1 + bn1; o.z = h2 + bn2; o.w = h3 + bn3;
            *reinterpret_cast<float4*>(C + (size_t)(m + 1) * 128 + nt * 4) = o;
        }
    }
}

// ---------------- CSR build ----------------
__global__ void zero_kernel(int* __restrict__ p, int N) {
    int i = blockIdx.x * blockDim.x + threadIdx.x;
    if (i < N) p[i] = 0;
}

__global__ void hist_kernel(const int* __restrict__ dst, int E, int N, int* __restrict__ cnt) {
    int i = blockIdx.x * blockDim.x + threadIdx.x;
    if (i < E + N) {
        int d = (i < E) ? dst[i] : (i - E);
        atomicAdd(cnt + d, 1);
    }
}

// inclusive scan of one 256-thread block via shuffles
__device__ __forceinline__ int block_incl_scan256(int v, int tid) {
    __shared__ int ws[8];
    int lane = tid & 31, wid = tid >> 5;
#pragma unroll
    for (int off = 1; off < 32; off <<= 1) {
        int t = __shfl_up_sync(0xffffffffu, v, off);
        if (lane >= off) v += t;
    }
    if (lane == 31) ws[wid] = v;
    __syncthreads();
    if (wid == 0) {
        int s = (lane < 8) ? ws[lane] : 0;
#pragma unroll
        for (int off = 1; off < 8; off <<= 1) {
            int t = __shfl_up_sync(0xffffffffu, s, off);
            if (lane >= off) s += t;
        }
        if (lane < 8) ws[lane] = s;
    }
    __syncthreads();
    if (wid > 0) v += ws[wid - 1];
    return v;
}

__global__ void scan1_kernel(const int* __restrict__ cnt, int N, int* __restrict__ rowptr, int* __restrict__ aux) {
    int t = threadIdx.x;
    int gid = blockIdx.x * 256 + t;
    int c = (gid < N) ? cnt[gid] : 0;
    int incl = block_incl_scan256(c, t);
    if (gid < N) rowptr[gid] = incl - c;   // block-local exclusive
    if (t == 255) aux[blockIdx.x] = incl;  // block total
}

__global__ void scan2_kernel(int* __restrict__ aux, int nb, int N, int Etot, int* __restrict__ rowptr) {
    int t = threadIdx.x;
    int v0 = (t < nb) ? aux[t] : 0;
    int incl = block_incl_scan256(v0, t);
    if (t < nb) aux[t] = incl - v0;        // exclusive block offsets
    if (t == 0) rowptr[N] = Etot;
}

__global__ void scan3_kernel(int* __restrict__ rowptr, const int* __restrict__ aux,
                             int* __restrict__ cursor, int N) {
    int gid = blockIdx.x * blockDim.x + threadIdx.x;
    if (gid < N) {
        int v = rowptr[gid] + aux[blockIdx.x];
        rowptr[gid] = v;
        cursor[gid] = v;
    }
}

__global__ void scatter_kernel(const int* __restrict__ src, const int* __restrict__ dst,
                               int E, int N, int* __restrict__ cursor, int* __restrict__ out) {
    int i = blockIdx.x * blockDim.x + threadIdx.x;
    if (i < E + N) {
        int s, d;
        if (i < E) { s = src[i]; d = dst[i]; }
        else       { s = i - E; d = i - E; }
        int pos = atomicAdd(cursor + d, 1);
        out[pos] = s;
    }
}

// ---------------- GAT edge softmax + aggregate (one warp per dst node, float4 lanes) ----------------
__global__ void edge_agg_kernel(const int* __restrict__ rowptr, const int* __restrict__ srcs,
                                const float* __restrict__ ai, const float* __restrict__ aj,
                                const float* __restrict__ y, float* __restrict__ out, int N)
{
    int w = (blockIdx.x * blockDim.x + threadIdx.x) >> 5;
    int lane = threadIdx.x & 31;
    if (w >= N) return;
    const int c = lane * 4;   // this lane's 4 contiguous feature columns
    float4 ai4 = *reinterpret_cast<const float4*>(ai + (size_t)w * 128 + c);
    float4 den = make_float4(0.f, 0.f, 0.f, 0.f);
    float4 num = make_float4(0.f, 0.f, 0.f, 0.f);
    int e0 = rowptr[w], e1 = rowptr[w + 1];
    int s_next = (e0 < e1) ? srcs[e0] : 0;
    for (int j = e0; j < e1; j++) {
        int s = s_next;
        if (j + 1 < e1) s_next = srcs[j + 1];
        float4 aj4 = *reinterpret_cast<const float4*>(aj + (size_t)s * 128 + c);
        float4 y4  = *reinterpret_cast<const float4*>(y  + (size_t)s * 128 + c);
        float a, e;
        a = ai4.x + aj4.x; a = fmaxf(a, 0.2f * a); e = __expf(a); den.x += e; num.x += e * y4.x;
        a = ai4.y + aj4.y; a = fmaxf(a, 0.2f * a); e = __expf(a); den.y += e; num.y += e * y4.y;
        a = ai4.z + aj4.z; a = fmaxf(a, 0.2f * a); e = __expf(a); den.z += e; num.z += e * y4.z;
        a = ai4.w + aj4.w; a = fmaxf(a, 0.2f * a); e = __expf(a); den.w += e; num.w += e * y4.w;
    }
    float4 o;
    o.x = num.x / (den.x + 1e-16f);
    o.y = num.y / (den.y + 1e-16f);
    o.z = num.z / (den.z + 1e-16f);
    o.w = num.w / (den.w + 1e-16f);
    *reinterpret_cast<float4*>(out + (size_t)w * 128 + c) = o;
}

// ---------------- GRU ----------------
__global__ void gru_kernel(const float* __restrict__ state, const float* __restrict__ input_,
                           const float* __restrict__ W_in, const float* __restrict__ W_z,
                           const float* __restrict__ W_r, const float* __restrict__ W_h,
                           float* __restrict__ h_out, float* __restrict__ h_out2, int L)
{
    __shared__ float mi[128], inp[128], st[128], rs[128], zz[128];
    int b = blockIdx.x, t = threadIdx.x;
    const float* ib = input_ + (size_t)b * L * 128;
    float s = 0.f;
    for (int l = 0; l < L; l++) s += ib[l * 128 + t];
    mi[t] = s / (float)L;
    st[t] = state[b * 128 + t];
    __syncthreads();
    {
        float acc = 0.f;
        const float* wr = W_in + t * 128;
        for (int d = 0; d < 128; d++) acc += mi[d] * wr[d];
        inp[t] = acc;
    }
    __syncthreads();
    float az = 0.f, ar = 0.f;
    {
        const float* wz = W_z + t * 256;
        const float* wr = W_r + t * 256;
        for (int d = 0; d < 128; d++) { az += st[d] * wz[d];        ar += st[d] * wr[d]; }
        for (int d = 0; d < 128; d++) { az += inp[d] * wz[128 + d]; ar += inp[d] * wr[128 + d]; }
    }
    float z = 1.f / (1.f + expf(-az));
    float r = 1.f / (1.f + expf(-ar));
    zz[t] = z;
    rs[t] = r * st[t];
    __syncthreads();
    float ah = 0.f;
    {
        const float* wh = W_h + t * 256;
        for (int d = 0; d < 128; d++) ah += rs[d] * wh[d];
        for (int d = 0; d < 128; d++) ah += inp[d] * wh[128 + d];
    }
    float ht = tanhf(ah);
    float h = (1.f - zz[t]) * st[t] + zz[t] * ht;
    h_out[b * 128 + t] = h;
    h_out2[b * 128 + t] = h;
}

// ---------------- head: prob logits + sisr (one warp per node, float4 lanes) ----------------
__global__ void head_kernel(const float* __restrict__ feat, const float* __restrict__ h,
                            const float* __restrict__ Wp, const float* __restrict__ bp,
                            const float* __restrict__ Wsv, const float* __restrict__ bsv,
                            float* __restrict__ praw, float* __restrict__ sisr, int N, int NN)
{
    int w = (blockIdx.x * blockDim.x + threadIdx.x) >> 5;
    int lane = threadIdx.x & 31;
    if (w >= N) return;
    int b = w / NN;
    const int c = lane * 4;
    float4 f  = *reinterpret_cast<const float4*>(feat + (size_t)w * 128 + c);
    float4 hh = *reinterpret_cast<const float4*>(h + b * 128 + c);
    float4 wp = *reinterpret_cast<const float4*>(Wp + c);
    float4 ws = *reinterpret_cast<const float4*>(Wsv + c);
    float4 xg;
    xg.x = f.x * hh.x; xg.y = f.y * hh.y; xg.z = f.z * hh.z; xg.w = f.w * hh.w;
    float p = xg.x * wp.x + xg.y * wp.y + xg.z * wp.z + xg.w * wp.w;
    float s = xg.x * ws.x + xg.y * ws.y + xg.z * ws.z + xg.w * ws.w;
    for (int off = 16; off; off >>= 1) {
        p += __shfl_xor_sync(0xffffffffu, p, off);
        s += __shfl_xor_sync(0xffffffffu, s, off);
    }
    if (lane == 0) {
        praw[w] = p + bp[0];
        sisr[w] = 1.f / (1.f + expf(-(s + bsv[0])));
    }
}

// ---------------- softmax over prob[:, 1:] per batch ----------------
__global__ void softmax_kernel(const float* __restrict__ praw, float* __restrict__ prob, int NN)
{
    __shared__ float red[512];
    int b = blockIdx.x, t = threadIdx.x;
    int n = t + 1;
    float v = (n < NN) ? praw[b * NN + n] : -1e30f;
    red[t] = v; __syncthreads();
    for (int off = 256; off; off >>= 1) {
        if (t < off) red[t] = fmaxf(red[t], red[t + off]);
        __syncthreads();
    }
    float m = red[0];
    __syncthreads();
    float e = (n < NN) ? expf(v - m) : 0.f;
    red[t] = e; __syncthreads();
    for (int off = 256; off; off >>= 1) {
        if (t < off) red[t] = red[t] + red[t + off];
        __syncthreads();
    }
    float sum = red[0];
    if (n < NN) prob[b * (NN - 1) + t] = e / sum;
}

// ---------------- launch ----------------
extern "C" void kernel_launch(void* const* d_in, const int* in_sizes, int n_in,
                              void* d_out, int out_size)
{
    const float* x      = (const float*)d_in[0];
    const int*   e0     = (const int*)  d_in[1];
    const int*   e1     = (const int*)  d_in[2];
    const float* state  = (const float*)d_in[3];
    const float* input_ = (const float*)d_in[4];
    const float* W_in   = (const float*)d_in[5];
    const float* W_z    = (const float*)d_in[6];
    const float* W_r    = (const float*)d_in[7];
    const float* W_h    = (const float*)d_in[8];
    const float* Wlin[2] = { (const float*)d_in[9],  (const float*)d_in[13] };
    const float* blin[2] = { (const float*)d_in[10], (const float*)d_in[14] };
    const float* Wat [2] = { (const float*)d_in[11], (const float*)d_in[15] };
    const float* bat [2] = { (const float*)d_in[12], (const float*)d_in[16] };
    const float* Wp     = (const float*)d_in[17];
    const float* bp     = (const float*)d_in[18];
    const float* Wsv    = (const float*)d_in[19];
    const float* bsv    = (const float*)d_in[20];

    const int N    = in_sizes[0] / 128;
    const int E    = in_sizes[1] / 2;
    const int B    = in_sizes[3] / 128;
    const int L    = in_sizes[4] / (B * 128);
    const int NN   = N / B;
    const int Etot = E + N;

    float *yp, *aip, *ajp, *featp, *hp, *prawp;
    int *cntp, *rowp, *curp, *srcp, *auxp;
    cudaGetSymbolAddress((void**)&yp,    g_y);
    cudaGetSymbolAddress((void**)&aip,   g_ai);
    cudaGetSymbolAddress((void**)&ajp,   g_aj);
    cudaGetSymbolAddress((void**)&featp, g_feat);
    cudaGetSymbolAddress((void**)&hp,    g_h);
    cudaGetSymbolAddress((void**)&prawp, g_praw);
    cudaGetSymbolAddress((void**)&cntp,  g_cnt);
    cudaGetSymbolAddress((void**)&rowp,  g_rowptr);
    cudaGetSymbolAddress((void**)&curp,  g_cursor);
    cudaGetSymbolAddress((void**)&srcp,  g_srcs);
    cudaGetSymbolAddress((void**)&auxp,  g_aux);

    float* out      = (float*)d_out;
    float* out_prob = out;
    float* out_sisr = out + (size_t)B * (NN - 1);
    float* out_h    = out + (size_t)B * (NN - 1) + (size_t)B * NN;

    cudaFuncSetAttribute(gemm128_kernel, cudaFuncAttributeMaxDynamicSharedMemorySize, GEMM_SMEM_BYTES);

    const int nbScan = (N + 255) / 256;
    const int gHist  = (Etot + 255) / 256;
    const int gWarp  = (N * 32 + 255) / 256;
    const int gGemm  = (N + 63) / 64;

    gru_kernel<<<B, 128>>>(state, input_, W_in, W_z, W_r, W_h, hp, out_h, L);

    for (int layer = 0; layer < 2; layer++) {
        const int* ei = layer ? e1 : e0;           // [2, E]: row 0 = src, row 1 = dst
        const float* Ain = layer ? featp : x;

        // CSR by dst (launch order chosen so the 6th launch overall is a GEMM for ncu)
        zero_kernel   <<<nbScan, 256>>>(cntp, N);
        hist_kernel   <<<gHist, 256>>>(ei + E, E, N, cntp);
        scan1_kernel  <<<nbScan, 256>>>(cntp, N, rowp, auxp);
        scan2_kernel  <<<1, 256>>>(auxp, nbScan, N, Etot, rowp);

        // node transforms (independent of CSR): y = A@Wlin^T + blin
        gemm128_kernel<<<gGemm, 256, GEMM_SMEM_BYTES>>>(Ain, Wlin[layer], 128, blin[layer], yp, N);

        scan3_kernel  <<<nbScan, 256>>>(rowp, auxp, curp, N);
        scatter_kernel<<<gHist, 256>>>(ei, ei + E, E, N, curp, srcp);

        // a_i = y@Wi^T + b_attn ; a_j = y@Wj^T
        gemm128_kernel<<<gGemm, 256, GEMM_SMEM_BYTES>>>(yp, Wat[layer], 256, bat[layer], aip, N);
        gemm128_kernel<<<gGemm, 256, GEMM_SMEM_BYTES>>>(yp, Wat[layer] + 128, 256, (const float*)nullptr, ajp, N);

        // softmax-weighted aggregation per dst node
        edge_agg_kernel<<<gWarp, 256>>>(rowp, srcp, aip, ajp, yp, featp, N);
    }

    head_kernel   <<<gWarp, 256>>>(featp, hp, Wp, bp, Wsv, bsv, prawp, out_sisr, N, NN);
    softmax_kernel<<<B, 512>>>(prawp, out_prob, NN);
}

// round 7
// speedup vs baseline: 1.4405x; 1.4405x over previous
#include <cuda_runtime.h>
#include <cstdint>
#include <cstdio>

// ---------------- problem-fixed constants ----------------
#define DD 128
#define MAXN 32000
#define MAXE 290000

// ---------------- scratch (static device globals; no allocs allowed) ----------------
__device__ __align__(16) float g_y   [MAXN * DD];
__device__ __align__(16) float g_ai  [MAXN * DD];
__device__ __align__(16) float g_aj  [MAXN * DD];
__device__ __align__(16) float g_feat[MAXN * DD];
__device__ __align__(16) float g_h   [64 * DD];
__device__ __align__(16) float g_praw[MAXN];
__device__ int g_cnt   [MAXN];
__device__ int g_rowptr[MAXN + 1];
__device__ int g_cursor[MAXN];
__device__ int g_srcs  [MAXE];
__device__ int g_aux   [256];

// ---------------- f32x2 helpers ----------------
__device__ __forceinline__ unsigned long long packdup(float v) {
    unsigned long long r;
    asm("mov.b64 %0, {%1, %1};" : "=l"(r) : "f"(v));
    return r;
}
__device__ __forceinline__ void fma2(unsigned long long& c, unsigned long long a, unsigned long long b) {
    asm("fma.rn.f32x2 %0, %1, %2, %0;" : "+l"(c) : "l"(a), "l"(b));
}
__device__ __forceinline__ void unpack2(unsigned long long v, float& lo, float& hi) {
    asm("mov.b64 {%0, %1}, %2;" : "=f"(lo), "=f"(hi) : "l"(v));
}

// ---------------- GEMM: C[M x 128] = A[M x 128] @ W[128 x 128]^T (+bias) ----------------
// R3-proven layout: k-major smem with padding; staging LDGs are coalesced
// (lane -> k, row-contiguous), STS conflicts accepted (gmem side matters more).
// blockIdx.y selects weight/output set (used to fuse the two attention GEMMs).
#define WS_STRIDE 132
#define XS_STRIDE 66
#define GEMM_SMEM_BYTES ((128 * WS_STRIDE + 128 * XS_STRIDE) * 4)

__global__ __launch_bounds__(256) void gemm128_kernel(
    const float* __restrict__ A,
    const float* __restrict__ W0, const float* __restrict__ b0, float* __restrict__ C0,
    const float* __restrict__ W1, const float* __restrict__ b1, float* __restrict__ C1,
    int wstride, int M)
{
    extern __shared__ float sm[];
    float* Ws = sm;                      // [128][WS_STRIDE]  (k-major)
    float* Xs = sm + 128 * WS_STRIDE;    // [128][XS_STRIDE]  (k-major)
    const int tid = threadIdx.x;
    const int m0 = blockIdx.x * 64;

    const float* W    = blockIdx.y ? W1 : W0;
    const float* bias = blockIdx.y ? b1 : b0;
    float*       C    = blockIdx.y ? C1 : C0;

    // stage W (coalesced: per-warp one row n, lanes span k)
    for (int i = tid; i < 128 * 32; i += 256) {
        int n = i >> 5, k = (i & 31) << 2;
        float4 w = *reinterpret_cast<const float4*>(W + (size_t)n * wstride + k);
        Ws[(k + 0) * WS_STRIDE + n] = w.x;
        Ws[(k + 1) * WS_STRIDE + n] = w.y;
        Ws[(k + 2) * WS_STRIDE + n] = w.z;
        Ws[(k + 3) * WS_STRIDE + n] = w.w;
    }
    // stage X (coalesced: per-warp one row m, lanes span k)
    for (int i = tid; i < 64 * 32; i += 256) {
        int m = i >> 5, k = (i & 31) << 2;
        float4 v = make_float4(0.f, 0.f, 0.f, 0.f);
        if (m0 + m < M) v = *reinterpret_cast<const float4*>(A + (size_t)(m0 + m) * 128 + k);
        Xs[(k + 0) * XS_STRIDE + m] = v.x;
        Xs[(k + 1) * XS_STRIDE + m] = v.y;
        Xs[(k + 2) * XS_STRIDE + m] = v.z;
        Xs[(k + 3) * XS_STRIDE + m] = v.w;
    }
    __syncthreads();

    const int mt = tid >> 5;     // warp -> rows mt*8..mt*8+7 (4 pairs)
    const int nt = tid & 31;     // lane -> cols nt*4..nt*4+3
    const float* wp = Ws + nt * 4;
    const float* xp = Xs + mt * 8;

    unsigned long long acc[4][4];
#pragma unroll
    for (int i = 0; i < 4; i++)
#pragma unroll
        for (int j = 0; j < 4; j++) acc[i][j] = 0ull;

#pragma unroll 4
    for (int k = 0; k < 128; k++) {
        float4 w = *reinterpret_cast<const float4*>(wp + k * WS_STRIDE);
        unsigned long long b0r = packdup(w.x), b1r = packdup(w.y), b2r = packdup(w.z), b3r = packdup(w.w);
        const unsigned long long* ap = reinterpret_cast<const unsigned long long*>(xp + k * XS_STRIDE);
        unsigned long long a0 = ap[0], a1 = ap[1], a2 = ap[2], a3 = ap[3];
        fma2(acc[0][0], a0, b0r); fma2(acc[0][1], a0, b1r); fma2(acc[0][2], a0, b2r); fma2(acc[0][3], a0, b3r);
        fma2(acc[1][0], a1, b0r); fma2(acc[1][1], a1, b1r); fma2(acc[1][2], a1, b2r); fma2(acc[1][3], a1, b3r);
        fma2(acc[2][0], a2, b0r); fma2(acc[2][1], a2, b1r); fma2(acc[2][2], a2, b2r); fma2(acc[2][3], a2, b3r);
        fma2(acc[3][0], a3, b0r); fma2(acc[3][1], a3, b1r); fma2(acc[3][2], a3, b2r); fma2(acc[3][3], a3, b3r);
    }

    float bn0 = 0.f, bn1 = 0.f, bn2 = 0.f, bn3 = 0.f;
    if (bias) { bn0 = bias[nt * 4]; bn1 = bias[nt * 4 + 1]; bn2 = bias[nt * 4 + 2]; bn3 = bias[nt * 4 + 3]; }

#pragma unroll
    for (int i = 0; i < 4; i++) {
        int m = m0 + mt * 8 + 2 * i;
        float l0, h0, l1, h1, l2, h2, l3, h3;
        unpack2(acc[i][0], l0, h0); unpack2(acc[i][1], l1, h1);
        unpack2(acc[i][2], l2, h2); unpack2(acc[i][3], l3, h3);
        if (m < M) {
            float4 o; o.x = l0 + bn0; o.y = l1 + bn1; o.z = l2 + bn2; o.w = l3 + bn3;
            *reinterpret_cast<float4*>(C + (size_t)m * 128 + nt * 4) = o;
        }
        if (m + 1 < M) {
            float4 o; o.x = h0 + bn0; o.y = h1 + bn1; o.z = h2 + bn2; o.w = h3 + bn3;
            *reinterpret_cast<float4*>(C + (size_t)(m + 1) * 128 + nt * 4) = o;
        }
    }
}

// ---------------- CSR build ----------------
__global__ void zero_kernel(int* __restrict__ p, int N) {
    int i = blockIdx.x * blockDim.x + threadIdx.x;
    if (i < N) p[i] = 0;
}

__global__ void hist_kernel(const int* __restrict__ dst, int E, int N, int* __restrict__ cnt) {
    int i = blockIdx.x * blockDim.x + threadIdx.x;
    if (i < E + N) {
        int d = (i < E) ? dst[i] : (i - E);
        atomicAdd(cnt + d, 1);
    }
}

// inclusive scan of one 256-thread block via shuffles
__device__ __forceinline__ int block_incl_scan256(int v, int tid) {
    __shared__ int ws[8];
    int lane = tid & 31, wid = tid >> 5;
#pragma unroll
    for (int off = 1; off < 32; off <<= 1) {
        int t = __shfl_up_sync(0xffffffffu, v, off);
        if (lane >= off) v += t;
    }
    if (lane == 31) ws[wid] = v;
    __syncthreads();
    if (wid == 0) {
        int s = (lane < 8) ? ws[lane] : 0;
#pragma unroll
        for (int off = 1; off < 8; off <<= 1) {
            int t = __shfl_up_sync(0xffffffffu, s, off);
            if (lane >= off) s += t;
        }
        if (lane < 8) ws[lane] = s;
    }
    __syncthreads();
    if (wid > 0) v += ws[wid - 1];
    return v;
}

__global__ void scan1_kernel(const int* __restrict__ cnt, int N, int* __restrict__ rowptr, int* __restrict__ aux) {
    int t = threadIdx.x;
    int gid = blockIdx.x * 256 + t;
    int c = (gid < N) ? cnt[gid] : 0;
    int incl = block_incl_scan256(c, t);
    if (gid < N) rowptr[gid] = incl - c;
    if (t == 255) aux[blockIdx.x] = incl;
}

__global__ void scan2_kernel(int* __restrict__ aux, int nb, int N, int Etot, int* __restrict__ rowptr) {
    int t = threadIdx.x;
    int v0 = (t < nb) ? aux[t] : 0;
    int incl = block_incl_scan256(v0, t);
    if (t < nb) aux[t] = incl - v0;
    if (t == 0) rowptr[N] = Etot;
}

__global__ void scan3_kernel(int* __restrict__ rowptr, const int* __restrict__ aux,
                             int* __restrict__ cursor, int N) {
    int gid = blockIdx.x * blockDim.x + threadIdx.x;
    if (gid < N) {
        int v = rowptr[gid] + aux[blockIdx.x];
        rowptr[gid] = v;
        cursor[gid] = v;
    }
}

__global__ void scatter_kernel(const int* __restrict__ src, const int* __restrict__ dst,
                               int E, int N, int* __restrict__ cursor, int* __restrict__ out) {
    int i = blockIdx.x * blockDim.x + threadIdx.x;
    if (i < E + N) {
        int s, d;
        if (i < E) { s = src[i]; d = dst[i]; }
        else       { s = i - E; d = i - E; }
        int pos = atomicAdd(cursor + d, 1);
        out[pos] = s;
    }
}

// ---------------- GAT edge softmax + aggregate (one warp per dst node, float4 lanes) ----------------
__global__ void edge_agg_kernel(const int* __restrict__ rowptr, const int* __restrict__ srcs,
                                const float* __restrict__ ai, const float* __restrict__ aj,
                                const float* __restrict__ y, float* __restrict__ out, int N)
{
    int w = (blockIdx.x * blockDim.x + threadIdx.x) >> 5;
    int lane = threadIdx.x & 31;
    if (w >= N) return;
    const int c = lane * 4;
    float4 ai4 = *reinterpret_cast<const float4*>(ai + (size_t)w * 128 + c);
    float4 den = make_float4(0.f, 0.f, 0.f, 0.f);
    float4 num = make_float4(0.f, 0.f, 0.f, 0.f);
    int e0 = rowptr[w], e1 = rowptr[w + 1];
    int s_next = (e0 < e1) ? srcs[e0] : 0;
    for (int j = e0; j < e1; j++) {
        int s = s_next;
        if (j + 1 < e1) s_next = srcs[j + 1];
        float4 aj4 = *reinterpret_cast<const float4*>(aj + (size_t)s * 128 + c);
        float4 y4  = *reinterpret_cast<const float4*>(y  + (size_t)s * 128 + c);
        float a, e;
        a = ai4.x + aj4.x; a = fmaxf(a, 0.2f * a); e = __expf(a); den.x += e; num.x += e * y4.x;
        a = ai4.y + aj4.y; a = fmaxf(a, 0.2f * a); e = __expf(a); den.y += e; num.y += e * y4.y;
        a = ai4.z + aj4.z; a = fmaxf(a, 0.2f * a); e = __expf(a); den.z += e; num.z += e * y4.z;
        a = ai4.w + aj4.w; a = fmaxf(a, 0.2f * a); e = __expf(a); den.w += e; num.w += e * y4.w;
    }
    float4 o;
    o.x = num.x / (den.x + 1e-16f);
    o.y = num.y / (den.y + 1e-16f);
    o.z = num.z / (den.z + 1e-16f);
    o.w = num.w / (den.w + 1e-16f);
    *reinterpret_cast<float4*>(out + (size_t)w * 128 + c) = o;
}

// ---------------- GRU ----------------
__global__ void gru_kernel(const float* __restrict__ state, const float* __restrict__ input_,
                           const float* __restrict__ W_in, const float* __restrict__ W_z,
                           const float* __restrict__ W_r, const float* __restrict__ W_h,
                           float* __restrict__ h_out, float* __restrict__ h_out2, int L)
{
    __shared__ float mi[128], inp[128], st[128], rs[128], zz[128];
    int b = blockIdx.x, t = threadIdx.x;
    const float* ib = input_ + (size_t)b * L * 128;
    float s = 0.f;
    for (int l = 0; l < L; l++) s += ib[l * 128 + t];
    mi[t] = s / (float)L;
    st[t] = state[b * 128 + t];
    __syncthreads();
    {
        float acc = 0.f;
        const float* wr = W_in + t * 128;
        for (int d = 0; d < 128; d++) acc += mi[d] * wr[d];
        inp[t] = acc;
    }
    __syncthreads();
    float az = 0.f, ar = 0.f;
    {
        const float* wz = W_z + t * 256;
        const float* wr = W_r + t * 256;
        for (int d = 0; d < 128; d++) { az += st[d] * wz[d];        ar += st[d] * wr[d]; }
        for (int d = 0; d < 128; d++) { az += inp[d] * wz[128 + d]; ar += inp[d] * wr[128 + d]; }
    }
    float z = 1.f / (1.f + expf(-az));
    float r = 1.f / (1.f + expf(-ar));
    zz[t] = z;
    rs[t] = r * st[t];
    __syncthreads();
    float ah = 0.f;
    {
        const float* wh = W_h + t * 256;
        for (int d = 0; d < 128; d++) ah += rs[d] * wh[d];
        for (int d = 0; d < 128; d++) ah += inp[d] * wh[128 + d];
    }
    float ht = tanhf(ah);
    float h = (1.f - zz[t]) * st[t] + zz[t] * ht;
    h_out[b * 128 + t] = h;
    h_out2[b * 128 + t] = h;
}

// ---------------- head: prob logits + sisr (one warp per node, float4 lanes) ----------------
__global__ void head_kernel(const float* __restrict__ feat, const float* __restrict__ h,
                            const float* __restrict__ Wp, const float* __restrict__ bp,
                            const float* __restrict__ Wsv, const float* __restrict__ bsv,
                            float* __restrict__ praw, float* __restrict__ sisr, int N, int NN)
{
    int w = (blockIdx.x * blockDim.x + threadIdx.x) >> 5;
    int lane = threadIdx.x & 31;
    if (w >= N) return;
    int b = w / NN;
    const int c = lane * 4;
    float4 f  = *reinterpret_cast<const float4*>(feat + (size_t)w * 128 + c);
    float4 hh = *reinterpret_cast<const float4*>(h + b * 128 + c);
    float4 wp = *reinterpret_cast<const float4*>(Wp + c);
    float4 ws = *reinterpret_cast<const float4*>(Wsv + c);
    float4 xg;
    xg.x = f.x * hh.x; xg.y = f.y * hh.y; xg.z = f.z * hh.z; xg.w = f.w * hh.w;
    float p = xg.x * wp.x + xg.y * wp.y + xg.z * wp.z + xg.w * wp.w;
    float s = xg.x * ws.x + xg.y * ws.y + xg.z * ws.z + xg.w * ws.w;
    for (int off = 16; off; off >>= 1) {
        p += __shfl_xor_sync(0xffffffffu, p, off);
        s += __shfl_xor_sync(0xffffffffu, s, off);
    }
    if (lane == 0) {
        praw[w] = p + bp[0];
        sisr[w] = 1.f / (1.f + expf(-(s + bsv[0])));
    }
}

// ---------------- softmax over prob[:, 1:] per batch ----------------
__global__ void softmax_kernel(const float* __restrict__ praw, float* __restrict__ prob, int NN)
{
    __shared__ float red[512];
    int b = blockIdx.x, t = threadIdx.x;
    int n = t + 1;
    float v = (n < NN) ? praw[b * NN + n] : -1e30f;
    red[t] = v; __syncthreads();
    for (int off = 256; off; off >>= 1) {
        if (t < off) red[t] = fmaxf(red[t], red[t + off]);
        __syncthreads();
    }
    float m = red[0];
    __syncthreads();
    float e = (n < NN) ? expf(v - m) : 0.f;
    red[t] = e; __syncthreads();
    for (int off = 256; off; off >>= 1) {
        if (t < off) red[t] = red[t] + red[t + off];
        __syncthreads();
    }
    float sum = red[0];
    if (n < NN) prob[b * (NN - 1) + t] = e / sum;
}

// ---------------- launch ----------------
extern "C" void kernel_launch(void* const* d_in, const int* in_sizes, int n_in,
                              void* d_out, int out_size)
{
    const float* x      = (const float*)d_in[0];
    const int*   e0     = (const int*)  d_in[1];
    const int*   e1     = (const int*)  d_in[2];
    const float* state  = (const float*)d_in[3];
    const float* input_ = (const float*)d_in[4];
    const float* W_in   = (const float*)d_in[5];
    const float* W_z    = (const float*)d_in[6];
    const float* W_r    = (const float*)d_in[7];
    const float* W_h    = (const float*)d_in[8];
    const float* Wlin[2] = { (const float*)d_in[9],  (const float*)d_in[13] };
    const float* blin[2] = { (const float*)d_in[10], (const float*)d_in[14] };
    const float* Wat [2] = { (const float*)d_in[11], (const float*)d_in[15] };
    const float* bat [2] = { (const float*)d_in[12], (const float*)d_in[16] };
    const float* Wp     = (const float*)d_in[17];
    const float* bp     = (const float*)d_in[18];
    const float* Wsv    = (const float*)d_in[19];
    const float* bsv    = (const float*)d_in[20];

    const int N    = in_sizes[0] / 128;
    const int E    = in_sizes[1] / 2;
    const int B    = in_sizes[3] / 128;
    const int L    = in_sizes[4] / (B * 128);
    const int NN   = N / B;
    const int Etot = E + N;

    float *yp, *aip, *ajp, *featp, *hp, *prawp;
    int *cntp, *rowp, *curp, *srcp, *auxp;
    cudaGetSymbolAddress((void**)&yp,    g_y);
    cudaGetSymbolAddress((void**)&aip,   g_ai);
    cudaGetSymbolAddress((void**)&ajp,   g_aj);
    cudaGetSymbolAddress((void**)&featp, g_feat);
    cudaGetSymbolAddress((void**)&hp,    g_h);
    cudaGetSymbolAddress((void**)&prawp, g_praw);
    cudaGetSymbolAddress((void**)&cntp,  g_cnt);
    cudaGetSymbolAddress((void**)&rowp,  g_rowptr);
    cudaGetSymbolAddress((void**)&curp,  g_cursor);
    cudaGetSymbolAddress((void**)&srcp,  g_srcs);
    cudaGetSymbolAddress((void**)&auxp,  g_aux);

    float* out      = (float*)d_out;
    float* out_prob = out;
    float* out_sisr = out + (size_t)B * (NN - 1);
    float* out_h    = out + (size_t)B * (NN - 1) + (size_t)B * NN;

    cudaFuncSetAttribute(gemm128_kernel, cudaFuncAttributeMaxDynamicSharedMemorySize, GEMM_SMEM_BYTES);

    const int nbScan = (N + 255) / 256;
    const int gHist  = (Etot + 255) / 256;
    const int gWarp  = (N * 32 + 255) / 256;
    const int gGemm  = (N + 63) / 64;
    dim3 grid1(gGemm, 1), grid2(gGemm, 2);

    gru_kernel<<<B, 128>>>(state, input_, W_in, W_z, W_r, W_h, hp, out_h, L);   // 1

    for (int layer = 0; layer < 2; layer++) {
        const int* ei = layer ? e1 : e0;           // [2, E]: row 0 = src, row 1 = dst
        const float* Ain = layer ? featp : x;

        zero_kernel   <<<nbScan, 256>>>(cntp, N);                               // 2
        hist_kernel   <<<gHist, 256>>>(ei + E, E, N, cntp);                     // 3

        // y = A@Wlin^T + blin   (4th launch overall -> ncu capture slot)
        gemm128_kernel<<<grid1, 256, GEMM_SMEM_BYTES>>>(
            Ain, Wlin[layer], blin[layer], yp,
            Wlin[layer], blin[layer], yp, 128, N);                              // 4

        scan1_kernel  <<<nbScan, 256>>>(cntp, N, rowp, auxp);                   // 5
        scan2_kernel  <<<1, 256>>>(auxp, nbScan, N, Etot, rowp);
        scan3_kernel  <<<nbScan, 256>>>(rowp, auxp, curp, N);
        scatter_kernel<<<gHist, 256>>>(ei, ei + E, E, N, curp, srcp);

        // fused: a_i = y@Wi^T + b_attn (blockIdx.y=0) ; a_j = y@Wj^T (blockIdx.y=1)
        gemm128_kernel<<<grid2, 256, GEMM_SMEM_BYTES>>>(
            yp, Wat[layer], bat[layer], aip,
            Wat[layer] + 128, (const float*)nullptr, ajp, 256, N);

        edge_agg_kernel<<<gWarp, 256>>>(rowp, srcp, aip, ajp, yp, featp, N);
    }

    head_kernel   <<<gWarp, 256>>>(featp, hp, Wp, bp, Wsv, bsv, prawp, out_sisr, N, NN);
    softmax_kernel<<<B, 512>>>(prawp, out_prob, NN);
}